// round 16
// baseline (speedup 1.0000x reference)
#include <cuda_runtime.h>
#include <cuda_fp16.h>
#include <cstdint>

#define B 2
#define S 2048
#define D 1024
#define H 16
#define DH 64
#define BS (B*S)
#define NW 4096   // 3072 qkv cols + 1024 out-proj cols

// Scratch (allocation-free rule: __device__ globals) — all fp16
__device__ __half g_Xh[BS*D];        // X converted to half
__device__ __half g_Qh[B*H*S*DH];    // [bh][s][e], pre-scaled by log2(e)/32
__device__ __half g_Kh[B*H*S*DH];    // [bh][s][e]
__device__ __half g_Vh[B*H*DH*S];    // TRANSPOSED [bh][e][s]
__device__ __half g_Oh[BS*D];        // attention output half [b*S+s][h*DH+e]
__device__ __half g_WTh[NW*D];       // transposed weights, half

#define QSCALE 0.04508687162f   // log2(e) / 32
#define ONES_H2 0x3C003C00u     // (1.0h, 1.0h)

__device__ __forceinline__ uint32_t smem_u32(const void* p) {
    uint32_t a;
    asm("{ .reg .u64 t; cvta.to.shared.u64 t, %1; cvt.u32.u64 %0, t; }"
        : "=r"(a) : "l"(p));
    return a;
}
// pack(lo, hi): lo -> low 16 bits
__device__ __forceinline__ uint32_t pack_h2(float lo, float hi) {
    uint32_t r;
    asm("cvt.rn.f16x2.f32 %0, %1, %2;" : "=r"(r) : "f"(hi), "f"(lo));
    return r;
}
__device__ __forceinline__ uint32_t h2exp2(uint32_t x) {
    uint32_t r;
    asm("ex2.approx.f16x2 %0, %1;" : "=r"(r) : "r"(x));
    return r;
}

#define MMA_F16(c, a, b)                                                    \
    asm volatile(                                                           \
        "mma.sync.aligned.m16n8k16.row.col.f32.f16.f16.f32 "                \
        "{%0,%1,%2,%3}, {%4,%5,%6,%7}, {%8,%9}, {%0,%1,%2,%3};"             \
        : "+f"((c)[0]), "+f"((c)[1]), "+f"((c)[2]), "+f"((c)[3])            \
        : "r"((a)[0]), "r"((a)[1]), "r"((a)[2]), "r"((a)[3]),               \
          "r"((b)[0]), "r"((b)[1]))

#define LDSM4(r0, r1, r2, r3, addr)                                         \
    asm volatile("ldmatrix.sync.aligned.m8n8.x4.shared.b16 {%0,%1,%2,%3}, [%4];" \
        : "=r"(r0), "=r"(r1), "=r"(r2), "=r"(r3) : "r"(addr))

#define CP16(dst, src) \
    asm volatile("cp.async.cg.shared.global [%0], [%1], 16;" :: "r"(dst), "l"(src))
#define CP_COMMIT() asm volatile("cp.async.commit_group;" ::: "memory")
#define CP_WAIT1()  asm volatile("cp.async.wait_group 1;" ::: "memory")
#define CP_WAIT0()  asm volatile("cp.async.wait_group 0;" ::: "memory")

// ===========================================================================
// Prep: X -> half
// ===========================================================================
__global__ void cvt_x(const float* __restrict__ X) {
    int i = (blockIdx.x * 256 + threadIdx.x) * 4;
    float4 v = *reinterpret_cast<const float4*>(X + i);
    *reinterpret_cast<__half2*>(&g_Xh[i])     = __floats2half2_rn(v.x, v.y);
    *reinterpret_cast<__half2*>(&g_Xh[i + 2]) = __floats2half2_rn(v.z, v.w);
}

// ===========================================================================
// Prep: weight transpose to half: g_WTh[n][d] = Wbig[d][n]
// ===========================================================================
__global__ void prep_wt(const float* __restrict__ Wq, const float* __restrict__ Wk,
                        const float* __restrict__ Wv, const float* __restrict__ Wo) {
    __shared__ float t[32][33];
    const int n0 = blockIdx.x * 32;
    const int d0 = blockIdx.y * 32;
    const int tx = threadIdx.x, ty = threadIdx.y;

    #pragma unroll
    for (int k = 0; k < 4; k++) {
        int d = d0 + ty + 8 * k;
        int n = n0 + tx;
        float v;
        if (n < 3072) {
            int z = n >> 10, h = (n >> 6) & 15, e = n & 63;
            const float* Wz = (z == 0) ? Wq : (z == 1) ? Wk : Wv;
            v = Wz[((size_t)h * D + d) * DH + e];
        } else {
            v = Wo[(size_t)d * D + (n - 3072)];
        }
        t[tx][ty + 8 * k] = v;
    }
    __syncthreads();
    #pragma unroll
    for (int k = 0; k < 4; k++) {
        int n = n0 + ty + 8 * k;
        int d = d0 + tx;
        g_WTh[(size_t)n * D + d] = __float2half_rn(t[ty + 8 * k][tx]);
    }
}

// ===========================================================================
// fp16 GEMM, warp tile 64x64 (4 warps 2x2, 128 threads, CTA 128x128).
// BK=64 (16 barrier rounds instead of 32), 3-stage cp.async, ONE barrier/iter
// with full lookahead. Tile rows stride 72 halfs (bank-verified).
//   mode 0: A = g_Xh, out -> g_Qh (scaled log2e/32) / g_Kh / g_Vh (transposed,
//           staged through smem for 64B-coalesced stores)
//   mode 1: A = g_Oh, out = Cout(fp32) + bias
// smem: 3 stages x (A 128x72 + B 128x72) halfs = 110592 B; 2 CTAs/SM.
// ===========================================================================
#define GT (128*72)   // one tile in halfs

__global__ __launch_bounds__(128, 2) void gemm_h(
    const float* __restrict__ bias,
    float* __restrict__ Cout,
    int nwbase, int mode)
{
    extern __shared__ __half smh[];
    const uint32_t sbase = smem_u32(smh);

    const int tid = threadIdx.x;
    const int wid = tid >> 5;        // 0..3
    const int lane = tid & 31;
    const int t = lane & 3;
    const int g = lane >> 2;
    const int wm = wid >> 1;         // 0..1
    const int wn = wid & 1;          // 0..1
    const int row0 = blockIdx.x * 128;
    const int n0 = blockIdx.y * 128;

    const int arow = ((lane & 8) ? 8 : 0) + (lane & 7);
    const int akoff = (lane >= 16) ? 8 : 0;
    const int brow = ((lane >= 16) ? 8 : 0) + (lane & 7);
    const int bkoff = (lane & 8) ? 8 : 0;

    const __half* Ah = (mode == 0) ? (const __half*)g_Xh : (const __half*)g_Oh;

    auto stage = [&](int k0, int buf) {
        const uint32_t ab = sbase + (2 * buf) * GT * 2;
        const uint32_t bb = sbase + (2 * buf + 1) * GT * 2;
        #pragma unroll
        for (int i = 0; i < 8; i++) {
            int f = tid + i * 128;           // [0,1024)
            int m = f >> 3, seg = f & 7;     // row 0..127, seg 0..7 (8 halfs each)
            CP16(ab + (m * 72 + seg * 8) * 2, Ah + (size_t)(row0 + m) * D + k0 + seg * 8);
            CP16(bb + (m * 72 + seg * 8) * 2, g_WTh + (size_t)(nwbase + n0 + m) * D + k0 + seg * 8);
        }
    };

    float c[4][8][4];
    #pragma unroll
    for (int mt = 0; mt < 4; mt++)
        #pragma unroll
        for (int nt = 0; nt < 8; nt++)
            #pragma unroll
            for (int q = 0; q < 4; q++) c[mt][nt][q] = 0.f;

    stage(0, 0);
    CP_COMMIT();
    stage(64, 1);
    CP_COMMIT();

    for (int it = 0; it < 16; it++) {
        if (it < 15) CP_WAIT1(); else CP_WAIT0();   // tile it arrived
        __syncthreads();                            // buf (it+2)%3 free
        if (it < 14) {
            stage((it + 2) * 64, (it + 2) % 3);
            CP_COMMIT();
        }

        const int buf = it % 3;
        const uint32_t Afb = sbase + (2 * buf) * GT * 2;
        const uint32_t Bfb = sbase + (2 * buf + 1) * GT * 2;
        #pragma unroll
        for (int ks = 0; ks < 4; ks++) {
            const int kb = ks * 16;
            uint32_t a[4][4], b[8][2];
            #pragma unroll
            for (int mt = 0; mt < 4; mt++) {
                int r = wm * 64 + mt * 16 + arow;
                LDSM4(a[mt][0], a[mt][1], a[mt][2], a[mt][3],
                      Afb + (r * 72 + kb + akoff) * 2);
            }
            #pragma unroll
            for (int np = 0; np < 4; np++) {
                int r = wn * 64 + np * 16 + brow;
                LDSM4(b[2 * np][0], b[2 * np][1], b[2 * np + 1][0], b[2 * np + 1][1],
                      Bfb + (r * 72 + kb + bkoff) * 2);
            }
            #pragma unroll
            for (int mt = 0; mt < 4; mt++)
                #pragma unroll
                for (int nt = 0; nt < 8; nt++)
                    MMA_F16(c[mt][nt], a[mt], b[nt]);
        }
    }

    // ======================= epilogue =======================
    if (mode == 0 && n0 >= 2048) {
        // --- V path: smem transpose for coalesced [e][s] stores ---
        __syncthreads();   // pipeline smem reads complete; safe to reuse
        #pragma unroll
        for (int mt = 0; mt < 4; mt++) {
            int mloc = wm * 64 + mt * 16 + g;
            #pragma unroll
            for (int nt = 0; nt < 8; nt++) {
                int nloc = wn * 64 + nt * 8 + 2 * t;
                smh[nloc * 136 + mloc]           = __float2half_rn(c[mt][nt][0]);
                smh[(nloc + 1) * 136 + mloc]     = __float2half_rn(c[mt][nt][1]);
                smh[nloc * 136 + mloc + 8]       = __float2half_rn(c[mt][nt][2]);
                smh[(nloc + 1) * 136 + mloc + 8] = __float2half_rn(c[mt][nt][3]);
            }
        }
        __syncthreads();
        const int bb = row0 >> 11;
        const int ss0 = row0 & (S - 1);
        #pragma unroll
        for (int pass = 0; pass < 4; pass++) {
            int nloc = (tid >> 2) + pass * 32;
            int m0 = (tid & 3) * 32;
            int ng = n0 + nloc;
            int rr = ng & 1023;
            int h = rr >> 6, e = rr & 63;
            __half* dst = g_Vh + ((size_t)(bb * H + h) * DH + e) * S + ss0 + m0;
            const __half* src = smh + nloc * 136 + m0;
            #pragma unroll
            for (int u = 0; u < 4; u++)
                reinterpret_cast<uint4*>(dst)[u] =
                    reinterpret_cast<const uint4*>(src)[u];
        }
        return;
    }

    #pragma unroll
    for (int mt = 0; mt < 4; mt++) {
        int m_lo = row0 + wm * 64 + mt * 16 + g;
        int m_hi = m_lo + 8;
        #pragma unroll
        for (int nt = 0; nt < 8; nt++) {
            int n = n0 + wn * 64 + nt * 8 + 2 * t;
            if (mode == 0) {
                int z = n >> 10, rr = n & 1023;
                int h = rr >> 6, e0 = rr & 63;
                int bb_lo = m_lo >> 11, ss_lo = m_lo & (S - 1);
                int bb_hi = m_hi >> 11, ss_hi = m_hi & (S - 1);
                if (z == 0) {
                    *reinterpret_cast<__half2*>(
                        g_Qh + ((size_t)(bb_lo * H + h) * S + ss_lo) * DH + e0) =
                        __floats2half2_rn(c[mt][nt][0] * QSCALE, c[mt][nt][1] * QSCALE);
                    *reinterpret_cast<__half2*>(
                        g_Qh + ((size_t)(bb_hi * H + h) * S + ss_hi) * DH + e0) =
                        __floats2half2_rn(c[mt][nt][2] * QSCALE, c[mt][nt][3] * QSCALE);
                } else {
                    *reinterpret_cast<__half2*>(
                        g_Kh + ((size_t)(bb_lo * H + h) * S + ss_lo) * DH + e0) =
                        __floats2half2_rn(c[mt][nt][0], c[mt][nt][1]);
                    *reinterpret_cast<__half2*>(
                        g_Kh + ((size_t)(bb_hi * H + h) * S + ss_hi) * DH + e0) =
                        __floats2half2_rn(c[mt][nt][2], c[mt][nt][3]);
                }
            } else {
                float2 bv = *reinterpret_cast<const float2*>(bias + n);
                *reinterpret_cast<float2*>(Cout + (size_t)m_lo * D + n) =
                    make_float2(c[mt][nt][0] + bv.x, c[mt][nt][1] + bv.y);
                *reinterpret_cast<float2*>(Cout + (size_t)m_hi * D + n) =
                    make_float2(c[mt][nt][2] + bv.x, c[mt][nt][3] + bv.y);
            }
        }
    }
}

// ===========================================================================
// Flash attention — EXACT R10/R14 version (measured 106 us fixed point):
// shift-free softmax with f16x2 exp2, ones-B MMA row sums, 3-stage cp.async,
// one barrier/iter. 256 thr, 128 q-rows/CTA.
// smem: 3 x (K[64][72]+V[64][72]) halfs = 55296 B
// ===========================================================================
#define KVTH (64*72)

__global__ __launch_bounds__(256, 2) void attn_h() {
    extern __shared__ __half smh[];
    const uint32_t sbase = smem_u32(smh);

    const int qt = blockIdx.x;
    const int bh = blockIdx.y;
    const __half* Qg = g_Qh + (size_t)bh * S * DH + (size_t)qt * 128 * DH;
    const __half* Kg = g_Kh + (size_t)bh * S * DH;
    const __half* Vg = g_Vh + (size_t)bh * DH * S;   // [e][s]

    const int tid = threadIdx.x;
    const int wid = tid >> 5;
    const int lane = tid & 31;
    const int t = lane & 3;
    const int g = lane >> 2;
    const int mrow = wid * 16 + g;

    const int brow = ((lane >= 16) ? 8 : 0) + (lane & 7);
    const int bkoff = (lane & 8) ? 8 : 0;

    auto stage = [&](int kt, int buf) {
        const uint32_t kb = sbase + buf * (2 * KVTH) * 2;
        const uint32_t vb = kb + KVTH * 2;
        #pragma unroll
        for (int i = 0; i < 2; i++) {
            int f = tid + i * 256;
            int r = f >> 3, seg = f & 7;
            CP16(kb + (r * 72 + seg * 8) * 2, Kg + ((size_t)kt * 64 + r) * DH + seg * 8);
            CP16(vb + (r * 72 + seg * 8) * 2, Vg + (size_t)r * S + kt * 64 + seg * 8);
        }
    };

    // --- persistent Q fragments (pre-scaled by log2e/32 at QKV epilogue) ---
    uint32_t qf[4][4];
    #pragma unroll
    for (int ks = 0; ks < 4; ks++) {
        qf[ks][0] = *reinterpret_cast<const uint32_t*>(Qg + (size_t)mrow * DH + 16 * ks + 2 * t);
        qf[ks][1] = *reinterpret_cast<const uint32_t*>(Qg + (size_t)(mrow + 8) * DH + 16 * ks + 2 * t);
        qf[ks][2] = *reinterpret_cast<const uint32_t*>(Qg + (size_t)mrow * DH + 16 * ks + 8 + 2 * t);
        qf[ks][3] = *reinterpret_cast<const uint32_t*>(Qg + (size_t)(mrow + 8) * DH + 16 * ks + 8 + 2 * t);
    }

    float oacc[8][4];
    #pragma unroll
    for (int nt = 0; nt < 8; nt++)
        #pragma unroll
        for (int q = 0; q < 4; q++) oacc[nt][q] = 0.f;
    float ol[4] = {0.f, 0.f, 0.f, 0.f};   // exact fp32 row sums of fp16 P
    const uint32_t bones[2] = {ONES_H2, ONES_H2};

    stage(0, 0);
    CP_COMMIT();
    stage(1, 1);
    CP_COMMIT();

    const int NT = S / 64;
    for (int kt = 0; kt < NT; kt++) {
        if (kt < NT - 1) CP_WAIT1(); else CP_WAIT0();
        __syncthreads();
        if (kt < NT - 2) {
            stage(kt + 2, (kt + 2) % 3);
            CP_COMMIT();
        }

        const uint32_t Kfb = sbase + (kt % 3) * (2 * KVTH) * 2;
        const uint32_t Vfb = Kfb + KVTH * 2;

        // --- S = Q K^T ---
        float s[8][4];
        #pragma unroll
        for (int nt = 0; nt < 8; nt++)
            #pragma unroll
            for (int q = 0; q < 4; q++) s[nt][q] = 0.f;

        #pragma unroll
        for (int ks = 0; ks < 4; ks++) {
            #pragma unroll
            for (int np = 0; np < 4; np++) {
                uint32_t b0, b1, b2, b3;
                LDSM4(b0, b1, b2, b3,
                      Kfb + ((16 * np + brow) * 72 + 16 * ks + bkoff) * 2);
                uint32_t be[2] = {b0, b1}, bo[2] = {b2, b3};
                MMA_F16(s[2 * np], qf[ks], be);
                MMA_F16(s[2 * np + 1], qf[ks], bo);
            }
        }

        // --- shift-free softmax: pack to fp16, f16x2 exp2 (16 MUFU ops) ---
        uint32_t p[8][2];
        #pragma unroll
        for (int nt = 0; nt < 8; nt++) {
            p[nt][0] = h2exp2(pack_h2(s[nt][0], s[nt][1]));
            p[nt][1] = h2exp2(pack_h2(s[nt][2], s[nt][3]));
        }

        // --- O += P @ V ; l += P @ 1 (independent accumulators, no chain) ---
        #pragma unroll
        for (int kk = 0; kk < 4; kk++) {
            uint32_t ap[4] = {p[2 * kk][0], p[2 * kk][1],
                              p[2 * kk + 1][0], p[2 * kk + 1][1]};
            MMA_F16(ol, ap, bones);
            #pragma unroll
            for (int np = 0; np < 4; np++) {
                uint32_t b0, b1, b2, b3;
                LDSM4(b0, b1, b2, b3,
                      Vfb + ((16 * np + brow) * 72 + 16 * kk + bkoff) * 2);
                uint32_t be[2] = {b0, b1}, bo[2] = {b2, b3};
                MMA_F16(oacc[2 * np], ap, be);
                MMA_F16(oacc[2 * np + 1], ap, bo);
            }
        }
    }

    // --- epilogue: normalize by ones-MMA sums (no shuffles needed) ---
    const float inv_lo = 1.f / ol[0];
    const float inv_hi = 1.f / ol[2];
    const int bb = bh >> 4, hh = bh & 15;
    const int row_lo = qt * 128 + wid * 16 + g;
    const int row_hi = row_lo + 8;
    #pragma unroll
    for (int nt = 0; nt < 8; nt++) {
        int e = 8 * nt + 2 * t;
        *reinterpret_cast<__half2*>(
            g_Oh + ((size_t)bb * S + row_lo) * D + hh * DH + e) =
            __floats2half2_rn(oacc[nt][0] * inv_lo, oacc[nt][1] * inv_lo);
        *reinterpret_cast<__half2*>(
            g_Oh + ((size_t)bb * S + row_hi) * D + hh * DH + e) =
            __floats2half2_rn(oacc[nt][2] * inv_hi, oacc[nt][3] * inv_hi);
    }
}

extern "C" void kernel_launch(void* const* d_in, const int* in_sizes, int n_in,
                              void* d_out, int out_size) {
    const float* X  = (const float*)d_in[0];
    const float* Wq = (const float*)d_in[1];
    const float* Wk = (const float*)d_in[2];
    const float* Wv = (const float*)d_in[3];
    const float* Wo = (const float*)d_in[4];
    const float* bo = (const float*)d_in[5];
    float* out = (float*)d_out;

    cvt_x<<<BS * D / (256 * 4), 256>>>(X);
    prep_wt<<<dim3(NW / 32, D / 32), dim3(32, 8)>>>(Wq, Wk, Wv, Wo);

    const int gemm_smem = 6 * GT * (int)sizeof(__half);  // 110592
    cudaFuncSetAttribute(gemm_h, cudaFuncAttributeMaxDynamicSharedMemorySize, gemm_smem);
    gemm_h<<<dim3(BS / 128, 24), 128, gemm_smem>>>(nullptr, nullptr, 0, 0);

    const int attn_smem = 6 * KVTH * (int)sizeof(__half);  // 55296
    cudaFuncSetAttribute(attn_h, cudaFuncAttributeMaxDynamicSharedMemorySize, attn_smem);
    attn_h<<<dim3(S / 128, B * H), 256, attn_smem>>>();

    gemm_h<<<dim3(BS / 128, 8), 128, gemm_smem>>>(bo, out, 3072, 1);
}

// round 17
// speedup vs baseline: 1.0560x; 1.0560x over previous
#include <cuda_runtime.h>
#include <cuda_fp16.h>
#include <cstdint>

#define B 2
#define S 2048
#define D 1024
#define H 16
#define DH 64
#define BS (B*S)
#define NW 4096   // 3072 qkv cols + 1024 out-proj cols

// Scratch (allocation-free rule: __device__ globals) — all fp16
__device__ __half g_Xh[BS*D];        // X converted to half
__device__ __half g_Qh[B*H*S*DH];    // [bh][s][e], pre-scaled by log2(e)/32
__device__ __half g_Kh[B*H*S*DH];    // [bh][s][e]
__device__ __half g_Vh[B*H*DH*S];    // TRANSPOSED [bh][e][s]
__device__ __half g_Oh[BS*D];        // attention output half [b*S+s][h*DH+e]
__device__ __half g_WTh[NW*D];       // transposed weights, half

#define QSCALE 0.04508687162f   // log2(e) / 32
#define ONES_H2 0x3C003C00u     // (1.0h, 1.0h)

__device__ __forceinline__ uint32_t smem_u32(const void* p) {
    uint32_t a;
    asm("{ .reg .u64 t; cvta.to.shared.u64 t, %1; cvt.u32.u64 %0, t; }"
        : "=r"(a) : "l"(p));
    return a;
}
// pack(lo, hi): lo -> low 16 bits
__device__ __forceinline__ uint32_t pack_h2(float lo, float hi) {
    uint32_t r;
    asm("cvt.rn.f16x2.f32 %0, %1, %2;" : "=r"(r) : "f"(hi), "f"(lo));
    return r;
}
__device__ __forceinline__ uint32_t h2exp2(uint32_t x) {
    uint32_t r;
    asm("ex2.approx.f16x2 %0, %1;" : "=r"(r) : "r"(x));
    return r;
}

#define MMA_F16(c, a, b)                                                    \
    asm volatile(                                                           \
        "mma.sync.aligned.m16n8k16.row.col.f32.f16.f16.f32 "                \
        "{%0,%1,%2,%3}, {%4,%5,%6,%7}, {%8,%9}, {%0,%1,%2,%3};"             \
        : "+f"((c)[0]), "+f"((c)[1]), "+f"((c)[2]), "+f"((c)[3])            \
        : "r"((a)[0]), "r"((a)[1]), "r"((a)[2]), "r"((a)[3]),               \
          "r"((b)[0]), "r"((b)[1]))

#define LDSM4(r0, r1, r2, r3, addr)                                         \
    asm volatile("ldmatrix.sync.aligned.m8n8.x4.shared.b16 {%0,%1,%2,%3}, [%4];" \
        : "=r"(r0), "=r"(r1), "=r"(r2), "=r"(r3) : "r"(addr))

#define CP16(dst, src) \
    asm volatile("cp.async.cg.shared.global [%0], [%1], 16;" :: "r"(dst), "l"(src))
#define CP_COMMIT() asm volatile("cp.async.commit_group;" ::: "memory")
#define CP_WAIT1()  asm volatile("cp.async.wait_group 1;" ::: "memory")
#define CP_WAIT0()  asm volatile("cp.async.wait_group 0;" ::: "memory")

// ===========================================================================
// Fused prep: blocks [0, 4096)   -> X -> half (256 thr, 1024 floats/blk)
//             blocks [4096, 8192) -> weight transpose tile (32x32)
// ===========================================================================
__global__ void prep_all(const float* __restrict__ X,
                         const float* __restrict__ Wq, const float* __restrict__ Wk,
                         const float* __restrict__ Wv, const float* __restrict__ Wo) {
    if (blockIdx.x < 4096) {
        int i = (blockIdx.x * 256 + threadIdx.x) * 4;
        float4 v = *reinterpret_cast<const float4*>(X + i);
        *reinterpret_cast<__half2*>(&g_Xh[i])     = __floats2half2_rn(v.x, v.y);
        *reinterpret_cast<__half2*>(&g_Xh[i + 2]) = __floats2half2_rn(v.z, v.w);
        return;
    }
    __shared__ float t[32][33];
    const int bid = blockIdx.x - 4096;       // [0, 4096)
    const int n0 = (bid & 127) * 32;          // 128 n-tiles
    const int d0 = (bid >> 7) * 32;           // 32 d-tiles
    const int tx = threadIdx.x & 31;
    const int ty = threadIdx.x >> 5;          // 0..7

    #pragma unroll
    for (int k = 0; k < 4; k++) {
        int d = d0 + ty + 8 * k;
        int n = n0 + tx;
        float v;
        if (n < 3072) {
            int z = n >> 10, h = (n >> 6) & 15, e = n & 63;
            const float* Wz = (z == 0) ? Wq : (z == 1) ? Wk : Wv;
            v = Wz[((size_t)h * D + d) * DH + e];
        } else {
            v = Wo[(size_t)d * D + (n - 3072)];
        }
        t[tx][ty + 8 * k] = v;
    }
    __syncthreads();
    #pragma unroll
    for (int k = 0; k < 4; k++) {
        int n = n0 + ty + 8 * k;
        int d = d0 + tx;
        g_WTh[(size_t)n * D + d] = __float2half_rn(t[ty + 8 * k][tx]);
    }
}

// ===========================================================================
// fp16 GEMM, warp tile 64x64 (4 warps 2x2, 128 threads, CTA 128x128).
// BK=32 (R15 exact — BK=64 measured 9us slower), 3-stage cp.async,
// ONE barrier/iter with full lookahead.
//   mode 0: A = g_Xh, out -> g_Qh (scaled log2e/32) / g_Kh / g_Vh (transposed,
//           staged through smem for 64B-coalesced stores)
//   mode 1: A = g_Oh, out = Cout(fp32) + bias
// smem: 6 tiles x 128x40 halfs = 61440 B; 2 CTAs/SM.
// ===========================================================================
#define GTS (128*40)

__global__ __launch_bounds__(128, 2) void gemm_h(
    const float* __restrict__ bias,
    float* __restrict__ Cout,
    int nwbase, int mode)
{
    extern __shared__ __half smh[];
    const uint32_t sbase = smem_u32(smh);

    const int tid = threadIdx.x;
    const int wid = tid >> 5;        // 0..3
    const int lane = tid & 31;
    const int t = lane & 3;
    const int g = lane >> 2;
    const int wm = wid >> 1;         // 0..1
    const int wn = wid & 1;          // 0..1
    const int row0 = blockIdx.x * 128;
    const int n0 = blockIdx.y * 128;

    const int arow = ((lane & 8) ? 8 : 0) + (lane & 7);
    const int akoff = (lane >= 16) ? 8 : 0;
    const int brow = ((lane >= 16) ? 8 : 0) + (lane & 7);
    const int bkoff = (lane & 8) ? 8 : 0;

    const __half* Ah = (mode == 0) ? (const __half*)g_Xh : (const __half*)g_Oh;

    auto stage = [&](int k0, int buf) {
        const uint32_t ab = sbase + (2 * buf) * GTS * 2;
        const uint32_t bb = sbase + (2 * buf + 1) * GTS * 2;
        #pragma unroll
        for (int i = 0; i < 4; i++) {
            int f = tid + i * 128;           // [0,512)
            int m = f >> 2, seg = f & 3;
            CP16(ab + (m * 40 + seg * 8) * 2, Ah + (size_t)(row0 + m) * D + k0 + seg * 8);
            CP16(bb + (m * 40 + seg * 8) * 2, g_WTh + (size_t)(nwbase + n0 + m) * D + k0 + seg * 8);
        }
    };

    float c[4][8][4];
    #pragma unroll
    for (int mt = 0; mt < 4; mt++)
        #pragma unroll
        for (int nt = 0; nt < 8; nt++)
            #pragma unroll
            for (int q = 0; q < 4; q++) c[mt][nt][q] = 0.f;

    stage(0, 0);
    CP_COMMIT();
    stage(32, 1);
    CP_COMMIT();

    for (int it = 0; it < 32; it++) {
        if (it < 31) CP_WAIT1(); else CP_WAIT0();
        __syncthreads();
        if (it < 30) {
            stage((it + 2) * 32, (it + 2) % 3);
            CP_COMMIT();
        }

        const int buf = it % 3;
        const uint32_t Afb = sbase + (2 * buf) * GTS * 2;
        const uint32_t Bfb = sbase + (2 * buf + 1) * GTS * 2;
        #pragma unroll
        for (int ks = 0; ks < 2; ks++) {
            const int kb = ks * 16;
            uint32_t a[4][4], b[8][2];
            #pragma unroll
            for (int mt = 0; mt < 4; mt++) {
                int r = wm * 64 + mt * 16 + arow;
                LDSM4(a[mt][0], a[mt][1], a[mt][2], a[mt][3],
                      Afb + (r * 40 + kb + akoff) * 2);
            }
            #pragma unroll
            for (int np = 0; np < 4; np++) {
                int r = wn * 64 + np * 16 + brow;
                LDSM4(b[2 * np][0], b[2 * np][1], b[2 * np + 1][0], b[2 * np + 1][1],
                      Bfb + (r * 40 + kb + bkoff) * 2);
            }
            #pragma unroll
            for (int mt = 0; mt < 4; mt++)
                #pragma unroll
                for (int nt = 0; nt < 8; nt++)
                    MMA_F16(c[mt][nt], a[mt], b[nt]);
        }
    }

    // ======================= epilogue =======================
    if (mode == 0 && n0 >= 2048) {
        // --- V path: smem transpose for coalesced [e][s] stores ---
        __syncthreads();   // pipeline smem reads complete; safe to reuse
        #pragma unroll
        for (int mt = 0; mt < 4; mt++) {
            int mloc = wm * 64 + mt * 16 + g;
            #pragma unroll
            for (int nt = 0; nt < 8; nt++) {
                int nloc = wn * 64 + nt * 8 + 2 * t;
                smh[nloc * 136 + mloc]           = __float2half_rn(c[mt][nt][0]);
                smh[(nloc + 1) * 136 + mloc]     = __float2half_rn(c[mt][nt][1]);
                smh[nloc * 136 + mloc + 8]       = __float2half_rn(c[mt][nt][2]);
                smh[(nloc + 1) * 136 + mloc + 8] = __float2half_rn(c[mt][nt][3]);
            }
        }
        __syncthreads();
        const int bb = row0 >> 11;
        const int ss0 = row0 & (S - 1);
        #pragma unroll
        for (int pass = 0; pass < 4; pass++) {
            int nloc = (tid >> 2) + pass * 32;
            int m0 = (tid & 3) * 32;
            int ng = n0 + nloc;
            int rr = ng & 1023;
            int h = rr >> 6, e = rr & 63;
            __half* dst = g_Vh + ((size_t)(bb * H + h) * DH + e) * S + ss0 + m0;
            const __half* src = smh + nloc * 136 + m0;
            #pragma unroll
            for (int u = 0; u < 4; u++)
                reinterpret_cast<uint4*>(dst)[u] =
                    reinterpret_cast<const uint4*>(src)[u];
        }
        return;
    }

    #pragma unroll
    for (int mt = 0; mt < 4; mt++) {
        int m_lo = row0 + wm * 64 + mt * 16 + g;
        int m_hi = m_lo + 8;
        #pragma unroll
        for (int nt = 0; nt < 8; nt++) {
            int n = n0 + wn * 64 + nt * 8 + 2 * t;
            if (mode == 0) {
                int z = n >> 10, rr = n & 1023;
                int h = rr >> 6, e0 = rr & 63;
                int bb_lo = m_lo >> 11, ss_lo = m_lo & (S - 1);
                int bb_hi = m_hi >> 11, ss_hi = m_hi & (S - 1);
                if (z == 0) {
                    *reinterpret_cast<__half2*>(
                        g_Qh + ((size_t)(bb_lo * H + h) * S + ss_lo) * DH + e0) =
                        __floats2half2_rn(c[mt][nt][0] * QSCALE, c[mt][nt][1] * QSCALE);
                    *reinterpret_cast<__half2*>(
                        g_Qh + ((size_t)(bb_hi * H + h) * S + ss_hi) * DH + e0) =
                        __floats2half2_rn(c[mt][nt][2] * QSCALE, c[mt][nt][3] * QSCALE);
                } else {
                    *reinterpret_cast<__half2*>(
                        g_Kh + ((size_t)(bb_lo * H + h) * S + ss_lo) * DH + e0) =
                        __floats2half2_rn(c[mt][nt][0], c[mt][nt][1]);
                    *reinterpret_cast<__half2*>(
                        g_Kh + ((size_t)(bb_hi * H + h) * S + ss_hi) * DH + e0) =
                        __floats2half2_rn(c[mt][nt][2], c[mt][nt][3]);
                }
            } else {
                float2 bv = *reinterpret_cast<const float2*>(bias + n);
                *reinterpret_cast<float2*>(Cout + (size_t)m_lo * D + n) =
                    make_float2(c[mt][nt][0] + bv.x, c[mt][nt][1] + bv.y);
                *reinterpret_cast<float2*>(Cout + (size_t)m_hi * D + n) =
                    make_float2(c[mt][nt][2] + bv.x, c[mt][nt][3] + bv.y);
            }
        }
    }
}

// ===========================================================================
// Flash attention — EXACT R10/R14/R15 version (measured 106 us fixed point):
// shift-free softmax with f16x2 exp2, ones-B MMA row sums, 3-stage cp.async,
// one barrier/iter. 256 thr, 128 q-rows/CTA.
// smem: 3 x (K[64][72]+V[64][72]) halfs = 55296 B
// ===========================================================================
#define KVTH (64*72)

__global__ __launch_bounds__(256, 2) void attn_h() {
    extern __shared__ __half smh[];
    const uint32_t sbase = smem_u32(smh);

    const int qt = blockIdx.x;
    const int bh = blockIdx.y;
    const __half* Qg = g_Qh + (size_t)bh * S * DH + (size_t)qt * 128 * DH;
    const __half* Kg = g_Kh + (size_t)bh * S * DH;
    const __half* Vg = g_Vh + (size_t)bh * DH * S;   // [e][s]

    const int tid = threadIdx.x;
    const int wid = tid >> 5;
    const int lane = tid & 31;
    const int t = lane & 3;
    const int g = lane >> 2;
    const int mrow = wid * 16 + g;

    const int brow = ((lane >= 16) ? 8 : 0) + (lane & 7);
    const int bkoff = (lane & 8) ? 8 : 0;

    auto stage = [&](int kt, int buf) {
        const uint32_t kb = sbase + buf * (2 * KVTH) * 2;
        const uint32_t vb = kb + KVTH * 2;
        #pragma unroll
        for (int i = 0; i < 2; i++) {
            int f = tid + i * 256;
            int r = f >> 3, seg = f & 7;
            CP16(kb + (r * 72 + seg * 8) * 2, Kg + ((size_t)kt * 64 + r) * DH + seg * 8);
            CP16(vb + (r * 72 + seg * 8) * 2, Vg + (size_t)r * S + kt * 64 + seg * 8);
        }
    };

    // --- persistent Q fragments (pre-scaled by log2e/32 at QKV epilogue) ---
    uint32_t qf[4][4];
    #pragma unroll
    for (int ks = 0; ks < 4; ks++) {
        qf[ks][0] = *reinterpret_cast<const uint32_t*>(Qg + (size_t)mrow * DH + 16 * ks + 2 * t);
        qf[ks][1] = *reinterpret_cast<const uint32_t*>(Qg + (size_t)(mrow + 8) * DH + 16 * ks + 2 * t);
        qf[ks][2] = *reinterpret_cast<const uint32_t*>(Qg + (size_t)mrow * DH + 16 * ks + 8 + 2 * t);
        qf[ks][3] = *reinterpret_cast<const uint32_t*>(Qg + (size_t)(mrow + 8) * DH + 16 * ks + 8 + 2 * t);
    }

    float oacc[8][4];
    #pragma unroll
    for (int nt = 0; nt < 8; nt++)
        #pragma unroll
        for (int q = 0; q < 4; q++) oacc[nt][q] = 0.f;
    float ol[4] = {0.f, 0.f, 0.f, 0.f};   // exact fp32 row sums of fp16 P
    const uint32_t bones[2] = {ONES_H2, ONES_H2};

    stage(0, 0);
    CP_COMMIT();
    stage(1, 1);
    CP_COMMIT();

    const int NT = S / 64;
    for (int kt = 0; kt < NT; kt++) {
        if (kt < NT - 1) CP_WAIT1(); else CP_WAIT0();
        __syncthreads();
        if (kt < NT - 2) {
            stage(kt + 2, (kt + 2) % 3);
            CP_COMMIT();
        }

        const uint32_t Kfb = sbase + (kt % 3) * (2 * KVTH) * 2;
        const uint32_t Vfb = Kfb + KVTH * 2;

        // --- S = Q K^T ---
        float s[8][4];
        #pragma unroll
        for (int nt = 0; nt < 8; nt++)
            #pragma unroll
            for (int q = 0; q < 4; q++) s[nt][q] = 0.f;

        #pragma unroll
        for (int ks = 0; ks < 4; ks++) {
            #pragma unroll
            for (int np = 0; np < 4; np++) {
                uint32_t b0, b1, b2, b3;
                LDSM4(b0, b1, b2, b3,
                      Kfb + ((16 * np + brow) * 72 + 16 * ks + bkoff) * 2);
                uint32_t be[2] = {b0, b1}, bo[2] = {b2, b3};
                MMA_F16(s[2 * np], qf[ks], be);
                MMA_F16(s[2 * np + 1], qf[ks], bo);
            }
        }

        // --- shift-free softmax: pack to fp16, f16x2 exp2 (16 MUFU ops) ---
        uint32_t p[8][2];
        #pragma unroll
        for (int nt = 0; nt < 8; nt++) {
            p[nt][0] = h2exp2(pack_h2(s[nt][0], s[nt][1]));
            p[nt][1] = h2exp2(pack_h2(s[nt][2], s[nt][3]));
        }

        // --- O += P @ V ; l += P @ 1 (independent accumulators, no chain) ---
        #pragma unroll
        for (int kk = 0; kk < 4; kk++) {
            uint32_t ap[4] = {p[2 * kk][0], p[2 * kk][1],
                              p[2 * kk + 1][0], p[2 * kk + 1][1]};
            MMA_F16(ol, ap, bones);
            #pragma unroll
            for (int np = 0; np < 4; np++) {
                uint32_t b0, b1, b2, b3;
                LDSM4(b0, b1, b2, b3,
                      Vfb + ((16 * np + brow) * 72 + 16 * kk + bkoff) * 2);
                uint32_t be[2] = {b0, b1}, bo[2] = {b2, b3};
                MMA_F16(oacc[2 * np], ap, be);
                MMA_F16(oacc[2 * np + 1], ap, bo);
            }
        }
    }

    // --- epilogue: normalize by ones-MMA sums (no shuffles needed) ---
    const float inv_lo = 1.f / ol[0];
    const float inv_hi = 1.f / ol[2];
    const int bb = bh >> 4, hh = bh & 15;
    const int row_lo = qt * 128 + wid * 16 + g;
    const int row_hi = row_lo + 8;
    #pragma unroll
    for (int nt = 0; nt < 8; nt++) {
        int e = 8 * nt + 2 * t;
        *reinterpret_cast<__half2*>(
            g_Oh + ((size_t)bb * S + row_lo) * D + hh * DH + e) =
            __floats2half2_rn(oacc[nt][0] * inv_lo, oacc[nt][1] * inv_lo);
        *reinterpret_cast<__half2*>(
            g_Oh + ((size_t)bb * S + row_hi) * D + hh * DH + e) =
            __floats2half2_rn(oacc[nt][2] * inv_hi, oacc[nt][3] * inv_hi);
    }
}

extern "C" void kernel_launch(void* const* d_in, const int* in_sizes, int n_in,
                              void* d_out, int out_size) {
    const float* X  = (const float*)d_in[0];
    const float* Wq = (const float*)d_in[1];
    const float* Wk = (const float*)d_in[2];
    const float* Wv = (const float*)d_in[3];
    const float* Wo = (const float*)d_in[4];
    const float* bo = (const float*)d_in[5];
    float* out = (float*)d_out;

    prep_all<<<8192, 256>>>(X, Wq, Wk, Wv, Wo);

    const int gemm_smem = 6 * GTS * (int)sizeof(__half);  // 61440
    cudaFuncSetAttribute(gemm_h, cudaFuncAttributeMaxDynamicSharedMemorySize, gemm_smem);
    gemm_h<<<dim3(BS / 128, 24), 128, gemm_smem>>>(nullptr, nullptr, 0, 0);

    const int attn_smem = 6 * KVTH * (int)sizeof(__half);  // 55296
    cudaFuncSetAttribute(attn_h, cudaFuncAttributeMaxDynamicSharedMemorySize, attn_smem);
    attn_h<<<dim3(S / 128, B * H), 256, attn_smem>>>();

    gemm_h<<<dim3(BS / 128, 8), 128, gemm_smem>>>(bo, out, 3072, 1);
}